// round 10
// baseline (speedup 1.0000x reference)
#include <cuda_runtime.h>
#include <cuda_bf16.h>
#include <math.h>
#include <stdint.h>

// ---------------------------------------------------------------------------
// SwinTransformerBlock on GB300: warp-MMA bf16 GEMMs (BK=64) + HMMA attention
// B=32, H=W=56, C=256, NH=8, hd=32, WS=7, SS=3
// ---------------------------------------------------------------------------

#define M_TOK   100352
#define C_DIM   256
#define NHEADS  8
#define HDIM    32
#define NWIN    2048
#define NSEQ    49

__device__ __nv_bfloat16 g_zw [(size_t)M_TOK * C_DIM];
__device__ __nv_bfloat16 g_qkv[(size_t)M_TOK * 768];
__device__ __nv_bfloat16 g_o  [(size_t)M_TOK * C_DIM];
__device__ float         g_x2 [(size_t)M_TOK * C_DIM];
__device__ __nv_bfloat16 g_h  [(size_t)M_TOK * C_DIM];
__device__ __nv_bfloat16 g_fc1[(size_t)M_TOK * 1024];
__device__ __nv_bfloat16 g_wqkvT[768 * 256];
__device__ __nv_bfloat16 g_wprojT[256 * 256];
__device__ __nv_bfloat16 g_wfc1T[1024 * 256];
__device__ __nv_bfloat16 g_wfc2T[256 * 1024];
__device__ float g_battn[NHEADS * NSEQ * NSEQ];

// ---------------------------------------------------------------------------
__device__ __forceinline__ uint32_t smem_u32(const void* p) {
    uint32_t a;
    asm("{ .reg .u64 t; cvta.to.shared.u64 t, %1; cvt.u32.u64 %0, t; }" : "=r"(a) : "l"(p));
    return a;
}
__device__ __forceinline__ void ldsm4(uint32_t* r, uint32_t addr) {
    asm volatile("ldmatrix.sync.aligned.m8n8.x4.shared.b16 {%0,%1,%2,%3}, [%4];"
                 : "=r"(r[0]), "=r"(r[1]), "=r"(r[2]), "=r"(r[3]) : "r"(addr));
}
__device__ __forceinline__ void mma16816(float* c, const uint32_t* a, const uint32_t* b) {
    asm volatile(
        "mma.sync.aligned.m16n8k16.row.col.f32.bf16.bf16.f32 "
        "{%0,%1,%2,%3}, {%4,%5,%6,%7}, {%8,%9}, {%0,%1,%2,%3};"
        : "+f"(c[0]), "+f"(c[1]), "+f"(c[2]), "+f"(c[3])
        : "r"(a[0]), "r"(a[1]), "r"(a[2]), "r"(a[3]), "r"(b[0]), "r"(b[1]));
}
__device__ __forceinline__ uint32_t pack2(float a, float b) {
    __nv_bfloat162 h = __floats2bfloat162_rn(a, b);
    return *(uint32_t*)&h;
}
// all-FMA exp: exp(x) = 2^(x*log2e), magic-number round + degree-4 poly.
__device__ __forceinline__ float fexp(float x) {
    float z = fmaxf(x * 1.4426950408889634f, -126.0f);
    float t = z + 12582912.0f;
    int   i = __float_as_int(t) - 0x4B400000;
    float f = z - (t - 12582912.0f);
    float p = 0.00961804886f;
    p = fmaf(p, f, 0.05550410866f);
    p = fmaf(p, f, 0.24022650696f);
    p = fmaf(p, f, 0.69314718056f);
    p = fmaf(p, f, 1.0f);
    return __int_as_float(__float_as_int(p) + (i << 23));
}
#define CP16(dst, src) asm volatile("cp.async.cg.shared.global [%0], [%1], 16;" :: "r"(dst), "l"(src))
#define CP_COMMIT()    asm volatile("cp.async.commit_group;" ::: "memory")
#define CP_WAIT1()     asm volatile("cp.async.wait_group 1;" ::: "memory")

// ---------------------------------------------------------------------------
__global__ void wconv_kernel(const float* __restrict__ in, __nv_bfloat16* __restrict__ out,
                             int K, int N)
{
    int id = blockIdx.x * 256 + threadIdx.x;
    if (id >= K * N) return;
    int n = id / K, k = id - n * K;
    out[id] = __float2bfloat16(in[(size_t)k * N + n]);
}

__global__ void bias_kernel(const float* __restrict__ rel_table,
                            const int* __restrict__ rel_idx,
                            float* __restrict__ out)
{
    int idx = blockIdx.x * 256 + threadIdx.x;
    if (idx >= NHEADS * NSEQ * NSEQ) return;
    int h = idx / (NSEQ * NSEQ), nm = idx % (NSEQ * NSEQ);
    out[idx] = rel_table[rel_idx[nm] * NHEADS + h];
}

// ---------------------------------------------------------------------------
// LayerNorm: warp-per-token. 8 tokens / block.
// ---------------------------------------------------------------------------
__global__ __launch_bounds__(256) void ln_kernel(
    const float* __restrict__ x,
    const float* __restrict__ gamma,
    const float* __restrict__ beta,
    __nv_bfloat16* __restrict__ out,
    int shifted)
{
    int wid = threadIdx.x >> 5, lane = threadIdx.x & 31;
    int t = blockIdx.x * 8 + wid;
    int src;
    if (shifted) {
        int wi  = t / NSEQ;
        int pos = t - wi * NSEQ;
        int b    = wi >> 6;
        int wrem = wi & 63;
        int hs = (wrem >> 3) * 7 + pos / 7;
        int ws = (wrem & 7) * 7 + pos % 7;
        int sh = hs + 3; if (sh >= 56) sh -= 56;
        int sw = ws + 3; if (sw >= 56) sw -= 56;
        src = b * 3136 + sh * 56 + sw;
    } else {
        src = t;
    }
    const float* row = x + (size_t)src * C_DIM + lane * 8;
    float4 v0 = *(const float4*)(row);
    float4 v1 = *(const float4*)(row + 4);
    float v[8] = {v0.x, v0.y, v0.z, v0.w, v1.x, v1.y, v1.z, v1.w};
    float s = 0.f, s2 = 0.f;
    #pragma unroll
    for (int i = 0; i < 8; i++) { s += v[i]; s2 += v[i] * v[i]; }
    #pragma unroll
    for (int off = 16; off; off >>= 1) {
        s  += __shfl_xor_sync(0xffffffffu, s,  off);
        s2 += __shfl_xor_sync(0xffffffffu, s2, off);
    }
    float mean = s * (1.f / 256.f);
    float var  = s2 * (1.f / 256.f) - mean * mean;
    float r = rsqrtf(var + 1e-6f);
    const float* g4 = gamma + lane * 8;
    const float* b4 = beta + lane * 8;
    uint32_t o4[4];
    #pragma unroll
    for (int i = 0; i < 4; i++) {
        float a0 = (v[2*i]   - mean) * r * g4[2*i]   + b4[2*i];
        float a1 = (v[2*i+1] - mean) * r * g4[2*i+1] + b4[2*i+1];
        o4[i] = pack2(a0, a1);
    }
    *(uint4*)(out + (size_t)t * C_DIM + lane * 8) = *(uint4*)o4;
}

// ---------------------------------------------------------------------------
// Warp-MMA bf16 GEMM: tile 128x128, BK=64, 128 threads, 64x64 warp tiles.
// 3-stage cp.async pipeline; per-chunk fixed cost amortized over 128 MMAs.
// ---------------------------------------------------------------------------
#define KP 72                         // 64 + 8 pad; 144B rows, conflict-free
#define STAGE_B (128 * KP * 2 * 2)    // 36864 bytes per stage (A+B)
#define B_OFF   (128 * KP * 2)        // 18432

template<int EPI>
__global__ __launch_bounds__(128) void gemm_bf16(
    const __nv_bfloat16* __restrict__ A,
    const __nv_bfloat16* __restrict__ Bt,
    const float* __restrict__ bias,
    const float* __restrict__ residual,
    void* __restrict__ outv,
    int K, int Nc)
{
    extern __shared__ __align__(16) uint8_t smem[];
    __shared__ float sbias[128];

    const int tid = threadIdx.x;
    const int lane = tid & 31, wid = tid >> 5;
    const int wm = wid & 1;
    const int wn = wid >> 1;
    const int bn = blockIdx.x * 128, bm = blockIdx.y * 128;

    sbias[tid] = bias[bn + tid];

    const uint32_t sBase = smem_u32(smem);

    // global->smem: warp covers 4 rows x 128B fully coalesced
    const int lr = tid >> 3;            // rows 0..15 (+j*16)
    const int lc = (tid & 7) * 8;       // col chunk (bf16 elems)

    const uint32_t aRowB = (uint32_t)(wm * 64 + (lane & 15));
    const uint32_t aKH   = (lane & 16) ? 8u : 0u;
    const uint32_t bRowB = (uint32_t)(wn * 64 + (lane & 7) + ((lane & 16) ? 8 : 0));
    const uint32_t bKH   = (lane & 8) ? 8u : 0u;

    float acc[4][8][4];
    #pragma unroll
    for (int i = 0; i < 4; i++)
        #pragma unroll
        for (int j = 0; j < 8; j++)
            #pragma unroll
            for (int t = 0; t < 4; t++) acc[i][j][t] = 0.f;

    const int nk = K >> 6;              // 64-wide chunks

    // prologue: stages 0,1
    #pragma unroll
    for (int s = 0; s < 2; s++) {
        uint32_t st = sBase + s * STAGE_B;
        const __nv_bfloat16* Ab = A + (size_t)bm * K + s * 64;
        const __nv_bfloat16* Bb = Bt + (size_t)bn * K + s * 64;
        #pragma unroll
        for (int j = 0; j < 8; j++) {
            int r = lr + j * 16;
            CP16(st + (uint32_t)(r * KP + lc) * 2,         Ab + (size_t)r * K + lc);
            CP16(st + B_OFF + (uint32_t)(r * KP + lc) * 2, Bb + (size_t)r * K + lc);
        }
        CP_COMMIT();
    }

    for (int kc = 0; kc < nk; kc++) {
        CP_WAIT1();
        __syncthreads();   // stage kc visible; prior reads of slot (kc+2)%3 done

        if (kc + 2 < nk) {
            uint32_t st = sBase + ((kc + 2) % 3) * STAGE_B;
            const __nv_bfloat16* Ab = A + (size_t)bm * K + (kc + 2) * 64;
            const __nv_bfloat16* Bb = Bt + (size_t)bn * K + (kc + 2) * 64;
            #pragma unroll
            for (int j = 0; j < 8; j++) {
                int r = lr + j * 16;
                CP16(st + (uint32_t)(r * KP + lc) * 2,         Ab + (size_t)r * K + lc);
                CP16(st + B_OFF + (uint32_t)(r * KP + lc) * 2, Bb + (size_t)r * K + lc);
            }
        }
        CP_COMMIT();

        const uint32_t aS = sBase + (kc % 3) * STAGE_B;
        const uint32_t bS = aS + B_OFF;
        #pragma unroll
        for (int ks = 0; ks < 4; ks++) {
            uint32_t af[4][4], bf[4][4];
            #pragma unroll
            for (int am = 0; am < 4; am++)
                ldsm4(af[am], aS + ((aRowB + am * 16) * KP + ks * 16 + aKH) * 2);
            #pragma unroll
            for (int g = 0; g < 4; g++)
                ldsm4(bf[g], bS + ((bRowB + g * 16) * KP + ks * 16 + bKH) * 2);
            #pragma unroll
            for (int am = 0; am < 4; am++)
                #pragma unroll
                for (int nn = 0; nn < 8; nn++)
                    mma16816(acc[am][nn], af[am], &bf[nn >> 1][(nn & 1) * 2]);
        }
    }

    const int n0 = bn + wn * 64 + (lane & 3) * 2;
    const int m0 = bm + wm * 64 + (lane >> 2);

    #pragma unroll
    for (int am = 0; am < 4; am++) {
        int mA = m0 + am * 16;
        int dstA = mA, dstB = mA + 8;
        if (EPI == 3) {
            #pragma unroll
            for (int h = 0; h < 2; h++) {
                int m = mA + h * 8;
                int wi  = m / NSEQ;
                int pos = m - wi * NSEQ;
                int b    = wi >> 6;
                int wrem = wi & 63;
                int hs = (wrem >> 3) * 7 + pos / 7;
                int ws = (wrem & 7) * 7 + pos % 7;
                int dh = hs + 3; if (dh >= 56) dh -= 56;
                int dw = ws + 3; if (dw >= 56) dw -= 56;
                int d = b * 3136 + dh * 56 + dw;
                if (h == 0) dstA = d; else dstB = d;
            }
        }
        #pragma unroll
        for (int nn = 0; nn < 8; nn++) {
            int col = n0 + nn * 8;
            float b0 = sbias[col - bn], b1 = sbias[col - bn + 1];
            float c0 = acc[am][nn][0] + b0, c1 = acc[am][nn][1] + b1;
            float c2 = acc[am][nn][2] + b0, c3 = acc[am][nn][3] + b1;
            if (EPI == 1) {
                c0 = c0 * 0.5f * (1.f + erff(c0 * 0.70710678118654752f));
                c1 = c1 * 0.5f * (1.f + erff(c1 * 0.70710678118654752f));
                c2 = c2 * 0.5f * (1.f + erff(c2 * 0.70710678118654752f));
                c3 = c3 * 0.5f * (1.f + erff(c3 * 0.70710678118654752f));
            }
            if (EPI == 0 || EPI == 1) {
                __nv_bfloat16* out = (__nv_bfloat16*)outv;
                *(uint32_t*)(out + (size_t)mA * Nc + col)       = pack2(c0, c1);
                *(uint32_t*)(out + (size_t)(mA + 8) * Nc + col) = pack2(c2, c3);
            } else {
                float* out = (float*)outv;
                float2 r0 = *(const float2*)(residual + (size_t)dstA * Nc + col);
                float2 r1 = *(const float2*)(residual + (size_t)dstB * Nc + col);
                *(float2*)(out + (size_t)dstA * Nc + col) = make_float2(c0 + r0.x, c1 + r0.y);
                *(float2*)(out + (size_t)dstB * Nc + col) = make_float2(c2 + r1.x, c3 + r1.y);
            }
        }
    }
}

// ---------------------------------------------------------------------------
// HMMA attention: one block per (window, head), 128 threads (4 warps).
// ---------------------------------------------------------------------------
#define QK_STRIDE 40
#define PB_STRIDE 72
#define S_STRIDE  66

__global__ __launch_bounds__(128) void attn_kernel(
    const __nv_bfloat16* __restrict__ qkv,
    const float* __restrict__ attn_mask,
    const float* __restrict__ battn,
    const float* __restrict__ temperature,
    __nv_bfloat16* __restrict__ o)
{
    __shared__ __align__(16) __nv_bfloat16 qb[64 * QK_STRIDE];
    __shared__ __align__(16) __nv_bfloat16 kb[64 * QK_STRIDE];
    __shared__ __align__(16) __nv_bfloat16 vT[32 * PB_STRIDE];
    __shared__ __align__(16) __nv_bfloat16 Pb[64 * PB_STRIDE];
    __shared__ float S[64 * S_STRIDE];

    const int wi = blockIdx.x;
    const int h  = blockIdx.y;
    const int tid = threadIdx.x;
    const int wr = tid >> 5, lane = tid & 31;

    const float scale = expf(temperature[0]);
    const __nv_bfloat16* base = qkv + (size_t)wi * NSEQ * 768 + h * HDIM;

    {
        uint4 z = make_uint4(0, 0, 0, 0);
        uint4* p = (uint4*)Pb;
        for (int i = tid; i < 64 * PB_STRIDE / 8; i += 128) p[i] = z;
        uint4* v = (uint4*)vT;
        for (int i = tid; i < 32 * PB_STRIDE / 8; i += 128) v[i] = z;
    }

    for (int idx = tid; idx < 392; idx += 128) {
        int ten = idx / 196;
        int r   = (idx % 196) >> 2;
        int c   = (idx & 3) * 8;
        uint4 u = *(const uint4*)(base + (size_t)r * 768 + ten * 256 + c);
        __nv_bfloat16* dst = ten ? kb : qb;
        *(uint4*)(dst + r * QK_STRIDE + c) = u;
    }
    for (int idx = tid; idx < NSEQ * HDIM; idx += 128) {
        int m = idx >> 5, d = idx & 31;
        vT[d * PB_STRIDE + m] = base[(size_t)m * 768 + 512 + d];
    }
    __syncthreads();

    const uint32_t qbB = smem_u32(qb), kbB = smem_u32(kb);
    const uint32_t vTB = smem_u32(vT), PbB = smem_u32(Pb);

    const uint32_t aRow = (uint32_t)(wr * 16 + (lane & 15));
    const uint32_t aKH  = (lane & 16) ? 8u : 0u;
    const uint32_t bRow = (uint32_t)((lane & 7) + ((lane & 16) ? 8 : 0));
    const uint32_t bKH  = (lane & 8) ? 8u : 0u;

    // ---- QK^T ----
    {
        float acc[8][4];
        #pragma unroll
        for (int j = 0; j < 8; j++)
            #pragma unroll
            for (int t = 0; t < 4; t++) acc[j][t] = 0.f;

        #pragma unroll
        for (int ks = 0; ks < 2; ks++) {
            uint32_t af[4], bf[4][4];
            ldsm4(af, qbB + (aRow * QK_STRIDE + ks * 16 + aKH) * 2);
            #pragma unroll
            for (int g = 0; g < 4; g++)
                ldsm4(bf[g], kbB + ((bRow + g * 16) * QK_STRIDE + ks * 16 + bKH) * 2);
            #pragma unroll
            for (int nn = 0; nn < 8; nn++)
                mma16816(acc[nn], af, &bf[nn >> 1][(nn & 1) * 2]);
        }

        int r0 = wr * 16 + (lane >> 2);
        int c0 = (lane & 3) * 2;
        #pragma unroll
        for (int nn = 0; nn < 8; nn++) {
            int c = c0 + nn * 8;
            S[r0 * S_STRIDE + c]           = acc[nn][0] * scale;
            S[r0 * S_STRIDE + c + 1]       = acc[nn][1] * scale;
            S[(r0 + 8) * S_STRIDE + c]     = acc[nn][2] * scale;
            S[(r0 + 8) * S_STRIDE + c + 1] = acc[nn][3] * scale;
        }
    }
    __syncthreads();

    // ---- softmax ----
    {
        const float* bia = battn + h * (NSEQ * NSEQ);
        const float* msk = attn_mask + (wi & 63) * (NSEQ * NSEQ);
        const float NEG = -3.402823466e38f;
        for (int n = wr; n < NSEQ; n += 4) {
            int m0 = lane, m1 = lane + 32;
            float s0 = S[n * S_STRIDE + m0];
            if (m0 == n) s0 = NEG;
            s0 += bia[n * NSEQ + m0] + msk[n * NSEQ + m0];
            float s1 = NEG;
            if (m1 < NSEQ) {
                s1 = S[n * S_STRIDE + m1];
                if (m1 == n) s1 = NEG;
                s1 += bia[n * NSEQ + m1] + msk[n * NSEQ + m1];
            }
            float mx = fmaxf(s0, s1);
            #pragma unroll
            for (int off = 16; off; off >>= 1)
                mx = fmaxf(mx, __shfl_xor_sync(0xffffffffu, mx, off));
            float e0 = fexp(s0 - mx);
            float e1 = (m1 < NSEQ) ? fexp(s1 - mx) : 0.f;
            float sum = e0 + e1;
            #pragma unroll
            for (int off = 16; off; off >>= 1)
                sum += __shfl_xor_sync(0xffffffffu, sum, off);
            float inv = 1.f / sum;
            Pb[n * PB_STRIDE + m0] = __float2bfloat16(e0 * inv);
            if (m1 < NSEQ) Pb[n * PB_STRIDE + m1] = __float2bfloat16(e1 * inv);
        }
    }
    __syncthreads();

    // ---- P*V ----
    {
        float acc[4][4];
        #pragma unroll
        for (int j = 0; j < 4; j++)
            #pragma unroll
            for (int t = 0; t < 4; t++) acc[j][t] = 0.f;

        #pragma unroll
        for (int ks = 0; ks < 4; ks++) {
            uint32_t af[4], bf[2][4];
            ldsm4(af, PbB + (aRow * PB_STRIDE + ks * 16 + aKH) * 2);
            #pragma unroll
            for (int g = 0; g < 2; g++)
                ldsm4(bf[g], vTB + ((bRow + g * 16) * PB_STRIDE + ks * 16 + bKH) * 2);
            #pragma unroll
            for (int nn = 0; nn < 4; nn++)
                mma16816(acc[nn], af, &bf[nn >> 1][(nn & 1) * 2]);
        }

        int n = wr * 16 + (lane >> 2);
        int d0 = (lane & 3) * 2;
        #pragma unroll
        for (int nn = 0; nn < 4; nn++) {
            int d = d0 + nn * 8;
            if (n < NSEQ)
                *(uint32_t*)(o + (size_t)(wi * NSEQ + n) * C_DIM + h * HDIM + d)
                    = pack2(acc[nn][0], acc[nn][1]);
            if (n + 8 < NSEQ)
                *(uint32_t*)(o + (size_t)(wi * NSEQ + n + 8) * C_DIM + h * HDIM + d)
                    = pack2(acc[nn][2], acc[nn][3]);
        }
    }
}

// ---------------------------------------------------------------------------
#define GEMM_SMEM (3 * STAGE_B)

extern "C" void kernel_launch(void* const* d_in, const int* in_sizes, int n_in,
                              void* d_out, int out_size)
{
    const float* x        = (const float*)d_in[0];
    const float* attn_msk = (const float*)d_in[1];
    const float* norm1_g  = (const float*)d_in[2];
    const float* norm1_b  = (const float*)d_in[3];
    const float* qkv_w    = (const float*)d_in[4];
    const float* qkv_b    = (const float*)d_in[5];
    const float* temp     = (const float*)d_in[6];
    const float* rel_tab  = (const float*)d_in[7];
    const float* proj_w   = (const float*)d_in[8];
    const float* proj_b   = (const float*)d_in[9];
    const float* norm2_g  = (const float*)d_in[10];
    const float* norm2_b  = (const float*)d_in[11];
    const float* fc1_w    = (const float*)d_in[12];
    const float* fc1_b    = (const float*)d_in[13];
    const float* fc2_w    = (const float*)d_in[14];
    const float* fc2_b    = (const float*)d_in[15];
    const int*   rel_idx  = (const int*)d_in[16];
    float* out = (float*)d_out;

    __nv_bfloat16 *zw, *qkv, *o, *hbuf, *fc1, *wqkvT, *wprojT, *wfc1T, *wfc2T;
    float *x2, *battn;
    cudaGetSymbolAddress((void**)&zw,    g_zw);
    cudaGetSymbolAddress((void**)&qkv,   g_qkv);
    cudaGetSymbolAddress((void**)&o,     g_o);
    cudaGetSymbolAddress((void**)&x2,    g_x2);
    cudaGetSymbolAddress((void**)&hbuf,  g_h);
    cudaGetSymbolAddress((void**)&fc1,   g_fc1);
    cudaGetSymbolAddress((void**)&wqkvT, g_wqkvT);
    cudaGetSymbolAddress((void**)&wprojT,g_wprojT);
    cudaGetSymbolAddress((void**)&wfc1T, g_wfc1T);
    cudaGetSymbolAddress((void**)&wfc2T, g_wfc2T);
    cudaGetSymbolAddress((void**)&battn, g_battn);

    static bool attr_done = false;
    if (!attr_done) {
        cudaFuncSetAttribute(gemm_bf16<0>, cudaFuncAttributeMaxDynamicSharedMemorySize, GEMM_SMEM);
        cudaFuncSetAttribute(gemm_bf16<1>, cudaFuncAttributeMaxDynamicSharedMemorySize, GEMM_SMEM);
        cudaFuncSetAttribute(gemm_bf16<2>, cudaFuncAttributeMaxDynamicSharedMemorySize, GEMM_SMEM);
        cudaFuncSetAttribute(gemm_bf16<3>, cudaFuncAttributeMaxDynamicSharedMemorySize, GEMM_SMEM);
        attr_done = true;
    }

    wconv_kernel<<<(256 * 768 + 255) / 256, 256>>>(qkv_w, wqkvT, 256, 768);          // 0
    ln_kernel<<<M_TOK / 8, 256>>>(x, norm1_g, norm1_b, zw, 1);                        // 1
    bias_kernel<<<(NHEADS * NSEQ * NSEQ + 255) / 256, 256>>>(rel_tab, rel_idx, battn);// 2
    gemm_bf16<0><<<dim3(6, M_TOK / 128), 128, GEMM_SMEM>>>(zw, wqkvT, qkv_b, nullptr, qkv, 256, 768); // 3
    wconv_kernel<<<(256 * 256 + 255) / 256, 256>>>(proj_w, wprojT, 256, 256);         // 4
    wconv_kernel<<<(256 * 1024 + 255) / 256, 256>>>(fc1_w, wfc1T, 256, 1024);         // 5
    wconv_kernel<<<(1024 * 256 + 255) / 256, 256>>>(fc2_w, wfc2T, 1024, 256);         // 6
    attn_kernel<<<dim3(NWIN, NHEADS), 128>>>(qkv, attn_msk, battn, temp, o);          // 7
    gemm_bf16<3><<<dim3(2, M_TOK / 128), 128, GEMM_SMEM>>>(o, wprojT, proj_b, x, x2, 256, 256); // 8
    ln_kernel<<<M_TOK / 8, 256>>>(x2, norm2_g, norm2_b, hbuf, 0);                     // 9
    gemm_bf16<1><<<dim3(8, M_TOK / 128), 128, GEMM_SMEM>>>(hbuf, wfc1T, fc1_b, nullptr, fc1, 256, 1024); // 10
    gemm_bf16<2><<<dim3(2, M_TOK / 128), 128, GEMM_SMEM>>>(fc1, wfc2T, fc2_b, x2, out, 1024, 256);       // 11
}

// round 11
// speedup vs baseline: 1.0749x; 1.0749x over previous
#include <cuda_runtime.h>
#include <cuda_bf16.h>
#include <math.h>
#include <stdint.h>

// ---------------------------------------------------------------------------
// SwinTransformerBlock on GB300: warp-MMA bf16 GEMMs + fused-window attention
// B=32, H=W=56, C=256, NH=8, hd=32, WS=7, SS=3
// ---------------------------------------------------------------------------

#define M_TOK   100352
#define C_DIM   256
#define NHEADS  8
#define HDIM    32
#define NWIN    2048
#define NSEQ    49

__device__ __nv_bfloat16 g_zw [(size_t)M_TOK * C_DIM];
__device__ __nv_bfloat16 g_qkv[(size_t)M_TOK * 768];
__device__ __nv_bfloat16 g_o  [(size_t)M_TOK * C_DIM];
__device__ float         g_x2 [(size_t)M_TOK * C_DIM];
__device__ __nv_bfloat16 g_h  [(size_t)M_TOK * C_DIM];
__device__ __nv_bfloat16 g_fc1[(size_t)M_TOK * 1024];
__device__ __nv_bfloat16 g_wqkvT[768 * 256];
__device__ __nv_bfloat16 g_wprojT[256 * 256];
__device__ __nv_bfloat16 g_wfc1T[1024 * 256];
__device__ __nv_bfloat16 g_wfc2T[256 * 1024];
__device__ float g_battn[NHEADS * NSEQ * NSEQ];

// ---------------------------------------------------------------------------
__device__ __forceinline__ uint32_t smem_u32(const void* p) {
    uint32_t a;
    asm("{ .reg .u64 t; cvta.to.shared.u64 t, %1; cvt.u32.u64 %0, t; }" : "=r"(a) : "l"(p));
    return a;
}
__device__ __forceinline__ void ldsm4(uint32_t* r, uint32_t addr) {
    asm volatile("ldmatrix.sync.aligned.m8n8.x4.shared.b16 {%0,%1,%2,%3}, [%4];"
                 : "=r"(r[0]), "=r"(r[1]), "=r"(r[2]), "=r"(r[3]) : "r"(addr));
}
__device__ __forceinline__ void mma16816(float* c, const uint32_t* a, const uint32_t* b) {
    asm volatile(
        "mma.sync.aligned.m16n8k16.row.col.f32.bf16.bf16.f32 "
        "{%0,%1,%2,%3}, {%4,%5,%6,%7}, {%8,%9}, {%0,%1,%2,%3};"
        : "+f"(c[0]), "+f"(c[1]), "+f"(c[2]), "+f"(c[3])
        : "r"(a[0]), "r"(a[1]), "r"(a[2]), "r"(a[3]), "r"(b[0]), "r"(b[1]));
}
__device__ __forceinline__ uint32_t pack2(float a, float b) {
    __nv_bfloat162 h = __floats2bfloat162_rn(a, b);
    return *(uint32_t*)&h;
}
// all-FMA exp
__device__ __forceinline__ float fexp(float x) {
    float z = fmaxf(x * 1.4426950408889634f, -126.0f);
    float t = z + 12582912.0f;
    int   i = __float_as_int(t) - 0x4B400000;
    float f = z - (t - 12582912.0f);
    float p = 0.00961804886f;
    p = fmaf(p, f, 0.05550410866f);
    p = fmaf(p, f, 0.24022650696f);
    p = fmaf(p, f, 0.69314718056f);
    p = fmaf(p, f, 1.0f);
    return __int_as_float(__float_as_int(p) + (i << 23));
}
#define CP16(dst, src) asm volatile("cp.async.cg.shared.global [%0], [%1], 16;" :: "r"(dst), "l"(src))
#define CP_COMMIT()    asm volatile("cp.async.commit_group;" ::: "memory")
#define CP_WAIT2()     asm volatile("cp.async.wait_group 2;" ::: "memory")

// ---------------------------------------------------------------------------
__global__ void wconv_kernel(const float* __restrict__ in, __nv_bfloat16* __restrict__ out,
                             int K, int N)
{
    int id = blockIdx.x * 256 + threadIdx.x;
    if (id >= K * N) return;
    int n = id / K, k = id - n * K;
    out[id] = __float2bfloat16(in[(size_t)k * N + n]);
}

__global__ void bias_kernel(const float* __restrict__ rel_table,
                            const int* __restrict__ rel_idx,
                            float* __restrict__ out)
{
    int idx = blockIdx.x * 256 + threadIdx.x;
    if (idx >= NHEADS * NSEQ * NSEQ) return;
    int h = idx / (NSEQ * NSEQ), nm = idx % (NSEQ * NSEQ);
    out[idx] = rel_table[rel_idx[nm] * NHEADS + h];
}

// ---------------------------------------------------------------------------
// LayerNorm: warp-per-token. 8 tokens / block.
// ---------------------------------------------------------------------------
__global__ __launch_bounds__(256) void ln_kernel(
    const float* __restrict__ x,
    const float* __restrict__ gamma,
    const float* __restrict__ beta,
    __nv_bfloat16* __restrict__ out,
    int shifted)
{
    int wid = threadIdx.x >> 5, lane = threadIdx.x & 31;
    int t = blockIdx.x * 8 + wid;
    int src;
    if (shifted) {
        int wi  = t / NSEQ;
        int pos = t - wi * NSEQ;
        int b    = wi >> 6;
        int wrem = wi & 63;
        int hs = (wrem >> 3) * 7 + pos / 7;
        int ws = (wrem & 7) * 7 + pos % 7;
        int sh = hs + 3; if (sh >= 56) sh -= 56;
        int sw = ws + 3; if (sw >= 56) sw -= 56;
        src = b * 3136 + sh * 56 + sw;
    } else {
        src = t;
    }
    const float* row = x + (size_t)src * C_DIM + lane * 8;
    float4 v0 = *(const float4*)(row);
    float4 v1 = *(const float4*)(row + 4);
    float v[8] = {v0.x, v0.y, v0.z, v0.w, v1.x, v1.y, v1.z, v1.w};
    float s = 0.f, s2 = 0.f;
    #pragma unroll
    for (int i = 0; i < 8; i++) { s += v[i]; s2 += v[i] * v[i]; }
    #pragma unroll
    for (int off = 16; off; off >>= 1) {
        s  += __shfl_xor_sync(0xffffffffu, s,  off);
        s2 += __shfl_xor_sync(0xffffffffu, s2, off);
    }
    float mean = s * (1.f / 256.f);
    float var  = s2 * (1.f / 256.f) - mean * mean;
    float r = rsqrtf(var + 1e-6f);
    const float* g4 = gamma + lane * 8;
    const float* b4 = beta + lane * 8;
    uint32_t o4[4];
    #pragma unroll
    for (int i = 0; i < 4; i++) {
        float a0 = (v[2*i]   - mean) * r * g4[2*i]   + b4[2*i];
        float a1 = (v[2*i+1] - mean) * r * g4[2*i+1] + b4[2*i+1];
        o4[i] = pack2(a0, a1);
    }
    *(uint4*)(out + (size_t)t * C_DIM + lane * 8) = *(uint4*)o4;
}

// ---------------------------------------------------------------------------
// Warp-MMA bf16 GEMM (R8-best config): tile 128x128, BK=32, 128 threads,
// 64x64 warp tiles, 4-stage cp.async.
// ---------------------------------------------------------------------------
#define KP 40
#define STAGE_B (128 * KP * 2 * 2)
#define B_OFF   (128 * KP * 2)

template<int EPI>
__global__ __launch_bounds__(128) void gemm_bf16(
    const __nv_bfloat16* __restrict__ A,
    const __nv_bfloat16* __restrict__ Bt,
    const float* __restrict__ bias,
    const float* __restrict__ residual,
    void* __restrict__ outv,
    int K, int Nc)
{
    extern __shared__ __align__(16) uint8_t smem[];
    __shared__ float sbias[128];

    const int tid = threadIdx.x;
    const int lane = tid & 31, wid = tid >> 5;
    const int wm = wid & 1;
    const int wn = wid >> 1;
    const int bn = blockIdx.x * 128, bm = blockIdx.y * 128;

    sbias[tid] = bias[bn + tid];

    const uint32_t sBase = smem_u32(smem);

    const int ldr0 = tid >> 2;
    const int ldc  = (tid & 3) * 8;

    const uint32_t aRowB = (uint32_t)(wm * 64 + (lane & 15));
    const uint32_t aKH   = (lane & 16) ? 8u : 0u;
    const uint32_t bRowB = (uint32_t)(wn * 64 + (lane & 7) + ((lane & 16) ? 8 : 0));
    const uint32_t bKH   = (lane & 8) ? 8u : 0u;

    float acc[4][8][4];
    #pragma unroll
    for (int i = 0; i < 4; i++)
        #pragma unroll
        for (int j = 0; j < 8; j++)
            #pragma unroll
            for (int t = 0; t < 4; t++) acc[i][j][t] = 0.f;

    const int nk = K >> 5;

    #pragma unroll
    for (int s = 0; s < 3; s++) {
        uint32_t st = sBase + s * STAGE_B;
        const __nv_bfloat16* Ab = A + (size_t)bm * K + s * 32;
        const __nv_bfloat16* Bb = Bt + (size_t)bn * K + s * 32;
        #pragma unroll
        for (int j = 0; j < 4; j++) {
            int r = ldr0 + j * 32;
            CP16(st + (uint32_t)(r * KP + ldc) * 2,         Ab + (size_t)r * K + ldc);
            CP16(st + B_OFF + (uint32_t)(r * KP + ldc) * 2, Bb + (size_t)r * K + ldc);
        }
        CP_COMMIT();
    }

    for (int kc = 0; kc < nk; kc++) {
        CP_WAIT2();
        __syncthreads();

        if (kc + 3 < nk) {
            uint32_t st = sBase + ((kc + 3) & 3) * STAGE_B;
            const __nv_bfloat16* Ab = A + (size_t)bm * K + (kc + 3) * 32;
            const __nv_bfloat16* Bb = Bt + (size_t)bn * K + (kc + 3) * 32;
            #pragma unroll
            for (int j = 0; j < 4; j++) {
                int r = ldr0 + j * 32;
                CP16(st + (uint32_t)(r * KP + ldc) * 2,         Ab + (size_t)r * K + ldc);
                CP16(st + B_OFF + (uint32_t)(r * KP + ldc) * 2, Bb + (size_t)r * K + ldc);
            }
        }
        CP_COMMIT();

        const uint32_t aS = sBase + (kc & 3) * STAGE_B;
        const uint32_t bS = aS + B_OFF;
        #pragma unroll
        for (int ks = 0; ks < 2; ks++) {
            uint32_t af[4][4], bf[4][4];
            #pragma unroll
            for (int am = 0; am < 4; am++)
                ldsm4(af[am], aS + ((aRowB + am * 16) * KP + ks * 16 + aKH) * 2);
            #pragma unroll
            for (int g = 0; g < 4; g++)
                ldsm4(bf[g], bS + ((bRowB + g * 16) * KP + ks * 16 + bKH) * 2);
            #pragma unroll
            for (int am = 0; am < 4; am++)
                #pragma unroll
                for (int nn = 0; nn < 8; nn++)
                    mma16816(acc[am][nn], af[am], &bf[nn >> 1][(nn & 1) * 2]);
        }
    }

    const int n0 = bn + wn * 64 + (lane & 3) * 2;
    const int m0 = bm + wm * 64 + (lane >> 2);

    #pragma unroll
    for (int am = 0; am < 4; am++) {
        int mA = m0 + am * 16;
        int dstA = mA, dstB = mA + 8;
        if (EPI == 3) {
            #pragma unroll
            for (int h = 0; h < 2; h++) {
                int m = mA + h * 8;
                int wi  = m / NSEQ;
                int pos = m - wi * NSEQ;
                int b    = wi >> 6;
                int wrem = wi & 63;
                int hs = (wrem >> 3) * 7 + pos / 7;
                int ws = (wrem & 7) * 7 + pos % 7;
                int dh = hs + 3; if (dh >= 56) dh -= 56;
                int dw = ws + 3; if (dw >= 56) dw -= 56;
                int d = b * 3136 + dh * 56 + dw;
                if (h == 0) dstA = d; else dstB = d;
            }
        }
        #pragma unroll
        for (int nn = 0; nn < 8; nn++) {
            int col = n0 + nn * 8;
            float b0 = sbias[col - bn], b1 = sbias[col - bn + 1];
            float c0 = acc[am][nn][0] + b0, c1 = acc[am][nn][1] + b1;
            float c2 = acc[am][nn][2] + b0, c3 = acc[am][nn][3] + b1;
            if (EPI == 1) {
                c0 = c0 * 0.5f * (1.f + erff(c0 * 0.70710678118654752f));
                c1 = c1 * 0.5f * (1.f + erff(c1 * 0.70710678118654752f));
                c2 = c2 * 0.5f * (1.f + erff(c2 * 0.70710678118654752f));
                c3 = c3 * 0.5f * (1.f + erff(c3 * 0.70710678118654752f));
            }
            if (EPI == 0 || EPI == 1) {
                __nv_bfloat16* out = (__nv_bfloat16*)outv;
                *(uint32_t*)(out + (size_t)mA * Nc + col)       = pack2(c0, c1);
                *(uint32_t*)(out + (size_t)(mA + 8) * Nc + col) = pack2(c2, c3);
            } else {
                float* out = (float*)outv;
                float2 r0 = *(const float2*)(residual + (size_t)dstA * Nc + col);
                float2 r1 = *(const float2*)(residual + (size_t)dstB * Nc + col);
                *(float2*)(out + (size_t)dstA * Nc + col) = make_float2(c0 + r0.x, c1 + r0.y);
                *(float2*)(out + (size_t)dstB * Nc + col) = make_float2(c2 + r1.x, c3 + r1.y);
            }
        }
    }
}

// ---------------------------------------------------------------------------
// Fused-window attention: one block per window, 256 threads, warp h = head h.
// QK^T (64 MMAs/warp) -> fragment softmax (no smem) -> P.V (64 MMAs/warp).
// Dynamic smem: qs/kb 8x64x40 bf16 + vT 8x32x72 bf16 = 118784 B.
// ---------------------------------------------------------------------------
#define AQ_STR 40
#define AV_STR 72
#define ATTN_QS   0
#define ATTN_KB   (8 * 64 * AQ_STR)               // elems
#define ATTN_VT   (ATTN_KB + 8 * 64 * AQ_STR)     // elems
#define ATTN_SMEM ((ATTN_VT + 8 * 32 * AV_STR) * 2)

__global__ __launch_bounds__(256) void attn_kernel(
    const __nv_bfloat16* __restrict__ qkv,
    const float* __restrict__ attn_mask,
    const float* __restrict__ battn,
    const float* __restrict__ temperature,
    __nv_bfloat16* __restrict__ o)
{
    extern __shared__ __align__(16) __nv_bfloat16 sm[];
    const int wi = blockIdx.x;
    const int tid = threadIdx.x;
    const int h = tid >> 5, lane = tid & 31;   // warp h handles head h

    const float scale = expf(temperature[0]);
    const __nv_bfloat16* base = qkv + (size_t)wi * NSEQ * 768;

    // zero vT (pads must be 0 for P*V)
    {
        uint4 z = make_uint4(0, 0, 0, 0);
        uint4* v = (uint4*)(sm + ATTN_VT);
        for (int i = tid; i < 8 * 32 * AV_STR / 8; i += 256) v[i] = z;
    }
    // load q/k/v: 49 rows x 96 uint4 (768 bf16) coalesced
    for (int idx = tid; idx < NSEQ * 96; idx += 256) {
        int r = idx / 96, u = idx - r * 96;
        int c0 = u * 8;
        uint4 val = *(const uint4*)(base + (size_t)r * 768 + c0);
        int ten = c0 >> 8;
        int within = c0 & 255;
        int hh = within >> 5, d = within & 31;
        if (ten == 0) {
            *(uint4*)(sm + ATTN_QS + hh * 64 * AQ_STR + r * AQ_STR + d) = val;
        } else if (ten == 1) {
            *(uint4*)(sm + ATTN_KB + hh * 64 * AQ_STR + r * AQ_STR + d) = val;
        } else {
            const __nv_bfloat16* e = (const __nv_bfloat16*)&val;
            __nv_bfloat16* vt = sm + ATTN_VT + hh * 32 * AV_STR;
            #pragma unroll
            for (int j = 0; j < 8; j++) vt[(d + j) * AV_STR + r] = e[j];
        }
    }
    __syncthreads();

    const uint32_t qB = smem_u32(sm + ATTN_QS + h * 64 * AQ_STR);
    const uint32_t kB = smem_u32(sm + ATTN_KB + h * 64 * AQ_STR);
    const uint32_t vB = smem_u32(sm + ATTN_VT + h * 32 * AV_STR);

    const uint32_t aRow = (uint32_t)(lane & 15);
    const uint32_t aKH  = (lane & 16) ? 8u : 0u;
    const uint32_t bRow = (uint32_t)((lane & 7) + ((lane & 16) ? 8 : 0));
    const uint32_t bKH  = (lane & 8) ? 8u : 0u;

    // ---- QK^T: 4 m-tiles x 8 n-tiles x 2 k-steps ----
    float acc[4][8][4];
    #pragma unroll
    for (int i = 0; i < 4; i++)
        #pragma unroll
        for (int j = 0; j < 8; j++)
            #pragma unroll
            for (int t = 0; t < 4; t++) acc[i][j][t] = 0.f;

    #pragma unroll
    for (int ks = 0; ks < 2; ks++) {
        uint32_t af[4][4], bf[4][4];
        #pragma unroll
        for (int am = 0; am < 4; am++)
            ldsm4(af[am], qB + ((aRow + am * 16) * AQ_STR + ks * 16 + aKH) * 2);
        #pragma unroll
        for (int g = 0; g < 4; g++)
            ldsm4(bf[g], kB + ((bRow + g * 16) * AQ_STR + ks * 16 + bKH) * 2);
        #pragma unroll
        for (int am = 0; am < 4; am++)
            #pragma unroll
            for (int nn = 0; nn < 8; nn++)
                mma16816(acc[am][nn], af[am], &bf[nn >> 1][(nn & 1) * 2]);
    }

    // ---- fragment softmax -> packed P a-frags ----
    const float* bia = battn + h * (NSEQ * NSEQ);
    const float* msk = attn_mask + (wi & 63) * (NSEQ * NSEQ);
    const float NEG = -3.402823466e38f;
    const int qlane = lane & 3;                 // quad col group
    uint32_t afP[4][4][4];

    #pragma unroll
    for (int am = 0; am < 4; am++) {
        #pragma unroll
        for (int half = 0; half < 2; half++) {
            int row = am * 16 + (lane >> 2) + half * 8;
            bool rv = row < NSEQ;
            float e[16];
            float mx = NEG;
            #pragma unroll
            for (int nt = 0; nt < 8; nt++) {
                #pragma unroll
                for (int j = 0; j < 2; j++) {
                    int col = nt * 8 + qlane * 2 + j;
                    float s = NEG;
                    if (rv && col < NSEQ && col != row)
                        s = acc[am][nt][half * 2 + j] * scale
                          + bia[row * NSEQ + col] + msk[row * NSEQ + col];
                    e[nt * 2 + j] = s;
                    mx = fmaxf(mx, s);
                }
            }
            mx = fmaxf(mx, __shfl_xor_sync(0xffffffffu, mx, 1));
            mx = fmaxf(mx, __shfl_xor_sync(0xffffffffu, mx, 2));
            float sum = 0.f;
            #pragma unroll
            for (int i = 0; i < 16; i++) { e[i] = fexp(e[i] - mx); sum += e[i]; }
            sum += __shfl_xor_sync(0xffffffffu, sum, 1);
            sum += __shfl_xor_sync(0xffffffffu, sum, 2);
            float inv = 1.f / sum;
            #pragma unroll
            for (int ks = 0; ks < 4; ks++) {
                uint32_t lo = pack2(e[4 * ks] * inv,     e[4 * ks + 1] * inv);
                uint32_t hi = pack2(e[4 * ks + 2] * inv, e[4 * ks + 3] * inv);
                // a0/a2 = row (half 0); a1/a3 = row+8 (half 1)
                afP[am][ks][half]     = lo;   // a0 or a1
                afP[am][ks][2 + half] = hi;   // a2 or a3
            }
        }
    }

    // ---- P*V: 4 m-tiles x 4 n-tiles (d=32) x 4 k-steps (m=64) ----
    float accP[4][4][4];
    #pragma unroll
    for (int i = 0; i < 4; i++)
        #pragma unroll
        for (int j = 0; j < 4; j++)
            #pragma unroll
            for (int t = 0; t < 4; t++) accP[i][j][t] = 0.f;

    #pragma unroll
    for (int ks = 0; ks < 4; ks++) {
        uint32_t bf[2][4];
        #pragma unroll
        for (int g = 0; g < 2; g++)
            ldsm4(bf[g], vB + ((bRow + g * 16) * AV_STR + ks * 16 + bKH) * 2);
        #pragma unroll
        for (int am = 0; am < 4; am++)
            #pragma unroll
            for (int nn = 0; nn < 4; nn++)
                mma16816(accP[am][nn], afP[am][ks], &bf[nn >> 1][(nn & 1) * 2]);
    }

    // ---- store ----
    #pragma unroll
    for (int am = 0; am < 4; am++) {
        int n = am * 16 + (lane >> 2);
        int d0 = qlane * 2;
        #pragma unroll
        for (int nn = 0; nn < 4; nn++) {
            int d = d0 + nn * 8;
            if (n < NSEQ)
                *(uint32_t*)(o + (size_t)(wi * NSEQ + n) * C_DIM + h * HDIM + d)
                    = pack2(accP[am][nn][0], accP[am][nn][1]);
            if (n + 8 < NSEQ)
                *(uint32_t*)(o + (size_t)(wi * NSEQ + n + 8) * C_DIM + h * HDIM + d)
                    = pack2(accP[am][nn][2], accP[am][nn][3]);
        }
    }
}

// ---------------------------------------------------------------------------
#define GEMM_SMEM (4 * STAGE_B)

extern "C" void kernel_launch(void* const* d_in, const int* in_sizes, int n_in,
                              void* d_out, int out_size)
{
    const float* x        = (const float*)d_in[0];
    const float* attn_msk = (const float*)d_in[1];
    const float* norm1_g  = (const float*)d_in[2];
    const float* norm1_b  = (const float*)d_in[3];
    const float* qkv_w    = (const float*)d_in[4];
    const float* qkv_b    = (const float*)d_in[5];
    const float* temp     = (const float*)d_in[6];
    const float* rel_tab  = (const float*)d_in[7];
    const float* proj_w   = (const float*)d_in[8];
    const float* proj_b   = (const float*)d_in[9];
    const float* norm2_g  = (const float*)d_in[10];
    const float* norm2_b  = (const float*)d_in[11];
    const float* fc1_w    = (const float*)d_in[12];
    const float* fc1_b    = (const float*)d_in[13];
    const float* fc2_w    = (const float*)d_in[14];
    const float* fc2_b    = (const float*)d_in[15];
    const int*   rel_idx  = (const int*)d_in[16];
    float* out = (float*)d_out;

    __nv_bfloat16 *zw, *qkv, *o, *hbuf, *fc1, *wqkvT, *wprojT, *wfc1T, *wfc2T;
    float *x2, *battn;
    cudaGetSymbolAddress((void**)&zw,    g_zw);
    cudaGetSymbolAddress((void**)&qkv,   g_qkv);
    cudaGetSymbolAddress((void**)&o,     g_o);
    cudaGetSymbolAddress((void**)&x2,    g_x2);
    cudaGetSymbolAddress((void**)&hbuf,  g_h);
    cudaGetSymbolAddress((void**)&fc1,   g_fc1);
    cudaGetSymbolAddress((void**)&wqkvT, g_wqkvT);
    cudaGetSymbolAddress((void**)&wprojT,g_wprojT);
    cudaGetSymbolAddress((void**)&wfc1T, g_wfc1T);
    cudaGetSymbolAddress((void**)&wfc2T, g_wfc2T);
    cudaGetSymbolAddress((void**)&battn, g_battn);

    static bool attr_done = false;
    if (!attr_done) {
        cudaFuncSetAttribute(gemm_bf16<0>, cudaFuncAttributeMaxDynamicSharedMemorySize, GEMM_SMEM);
        cudaFuncSetAttribute(gemm_bf16<1>, cudaFuncAttributeMaxDynamicSharedMemorySize, GEMM_SMEM);
        cudaFuncSetAttribute(gemm_bf16<2>, cudaFuncAttributeMaxDynamicSharedMemorySize, GEMM_SMEM);
        cudaFuncSetAttribute(gemm_bf16<3>, cudaFuncAttributeMaxDynamicSharedMemorySize, GEMM_SMEM);
        cudaFuncSetAttribute(attn_kernel, cudaFuncAttributeMaxDynamicSharedMemorySize, ATTN_SMEM);
        attr_done = true;
    }

    wconv_kernel<<<(256 * 768 + 255) / 256, 256>>>(qkv_w, wqkvT, 256, 768);          // 0
    ln_kernel<<<M_TOK / 8, 256>>>(x, norm1_g, norm1_b, zw, 1);                        // 1
    bias_kernel<<<(NHEADS * NSEQ * NSEQ + 255) / 256, 256>>>(rel_tab, rel_idx, battn);// 2
    gemm_bf16<0><<<dim3(6, M_TOK / 128), 128, GEMM_SMEM>>>(zw, wqkvT, qkv_b, nullptr, qkv, 256, 768); // 3
    wconv_kernel<<<(256 * 256 + 255) / 256, 256>>>(proj_w, wprojT, 256, 256);         // 4
    wconv_kernel<<<(256 * 1024 + 255) / 256, 256>>>(fc1_w, wfc1T, 256, 1024);         // 5
    wconv_kernel<<<(1024 * 256 + 255) / 256, 256>>>(fc2_w, wfc2T, 1024, 256);         // 6
    attn_kernel<<<NWIN, 256, ATTN_SMEM>>>(qkv, attn_msk, battn, temp, o);             // 7
    gemm_bf16<3><<<dim3(2, M_TOK / 128), 128, GEMM_SMEM>>>(o, wprojT, proj_b, x, x2, 256, 256); // 8
    ln_kernel<<<M_TOK / 8, 256>>>(x2, norm2_g, norm2_b, hbuf, 0);                     // 9
    gemm_bf16<1><<<dim3(8, M_TOK / 128), 128, GEMM_SMEM>>>(hbuf, wfc1T, fc1_b, nullptr, fc1, 256, 1024); // 10
    gemm_bf16<2><<<dim3(2, M_TOK / 128), 128, GEMM_SMEM>>>(fc1, wfc2T, fc2_b, x2, out, 1024, 256);       // 11
}